// round 9
// baseline (speedup 1.0000x reference)
#include <cuda_runtime.h>
#include <cuda_bf16.h>
#include <cstdint>
#include <math.h>

// ---------------------------------------------------------------------------
// Problem constants
// ---------------------------------------------------------------------------
#define BATCH 8192
#define TDIM  512
#define FDIM  2048
#define NATTN 4
#define NMLP  2

// weight scratch layout (element offsets into g_wh / g_wl)
// [MS_OFF)  : packed mu/sig, per attn block 1024x512, rows interleaved
//             (even row r -> mu_w[r/2], odd row r -> sg_w[r/2])
#define MS_OFF  0
#define AW1_OFF 2097152
#define AW2_OFF 6291456
#define MW1_OFF 10485760
#define MW2_OFF 12582912
#define WTOTAL  14680064

// ---------------------------------------------------------------------------
// Device scratch (static — no allocation at launch time)
// ---------------------------------------------------------------------------
__device__ __nv_bfloat16 g_wh[WTOTAL];          // 29 MB  weight hi
__device__ __nv_bfloat16 g_wl[WTOTAL];          // 29 MB  weight lo
__device__ float         g_Q [BATCH * TDIM];    // 16 MB  residual stream
__device__ float         g_H [BATCH * TDIM * 8];// 128 MB RFF tokens (precomputed)
__device__ __nv_bfloat16 g_hh[BATCH * TDIM];    // LN output hi
__device__ __nv_bfloat16 g_hl[BATCH * TDIM];    // LN output lo
__device__ __nv_bfloat16 g_th[BATCH * FDIM];    // FFN mid hi
__device__ __nv_bfloat16 g_tl[BATCH * FDIM];    // FFN mid lo

// ---------------------------------------------------------------------------
// Helpers
// ---------------------------------------------------------------------------
__device__ __forceinline__ float silu_f(float x) {
    return x / (1.0f + __expf(-x));
}

__device__ __forceinline__ void split_bf16(float x, __nv_bfloat16& hi, __nv_bfloat16& lo) {
    hi = __float2bfloat16_rn(x);
    lo = __float2bfloat16_rn(x - __bfloat162float(hi));
}

__device__ __forceinline__ void mma_bf16(float* d, const uint32_t* a, const uint32_t* b) {
    asm volatile(
        "mma.sync.aligned.m16n8k16.row.col.f32.bf16.bf16.f32 "
        "{%0,%1,%2,%3}, {%4,%5,%6,%7}, {%8,%9}, {%0,%1,%2,%3};\n"
        : "+f"(d[0]), "+f"(d[1]), "+f"(d[2]), "+f"(d[3])
        : "r"(a[0]), "r"(a[1]), "r"(a[2]), "r"(a[3]), "r"(b[0]), "r"(b[1]));
}

__device__ __forceinline__ void cp16(uint32_t dst, const void* src) {
    asm volatile("cp.async.cg.shared.global [%0], [%1], 16;\n" :: "r"(dst), "l"(src));
}
__device__ __forceinline__ void cp_commit() {
    asm volatile("cp.async.commit_group;\n");
}
template<int N> __device__ __forceinline__ void cp_wait() {
    asm volatile("cp.async.wait_group %0;\n" :: "n"(N));
}

__device__ __forceinline__ void ldsm4(uint32_t& r0, uint32_t& r1, uint32_t& r2,
                                      uint32_t& r3, uint32_t addr) {
    asm volatile("ldmatrix.sync.aligned.m8n8.x4.shared.b16 {%0,%1,%2,%3}, [%4];\n"
                 : "=r"(r0), "=r"(r1), "=r"(r2), "=r"(r3) : "r"(addr));
}

// ---------------------------------------------------------------------------
// GEMM mainloop v2 (bf16x3 split):
//   512 threads, 1 CTA/SM. Warp grid 4m x 4n, warp tile 32x32 -> acc 32 regs,
//   leaving room to preload ALL fragments (both k-halves, hi+lo) before the
//   MMA burst: 16 ldmatrix then 96 MMAs, acc-reuse distance 8.
//   5-stage cp.async ring (200KB smem), ONE __syncthreads per K-tile:
//   buffer restaged at iter it ((it+4)%5) was last read at iter it-1, and all
//   warps passed this iteration's barrier after finishing it-1's MMAs.
// smem row: 16 uint32 (32 bf16) + 4 pad = stride 20 -> conflict-free ldmatrix.
// ---------------------------------------------------------------------------
#define SSTR 20
#define ARR_BYTES   (128 * SSTR * 4)   // 10240
#define STAGE_BYTES (4 * ARR_BYTES)    // 40960: Ahi, Alo, Whi, Wlo
#define NSTAGE 5
#define SMEM_BYTES  (NSTAGE * STAGE_BYTES)  // 204800
#define NTHREADS 512

template<int K>
__device__ __forceinline__ void gemm_mainloop(
    const __nv_bfloat16* __restrict__ Ah, const __nv_bfloat16* __restrict__ Al,
    const __nv_bfloat16* __restrict__ Wh, const __nv_bfloat16* __restrict__ Wl,
    int rowBase, int colBase, uint32_t sb, float acc[2][4][4])
{
    const int tid  = threadIdx.x;
    const int lane = tid & 31;
    const int warp = tid >> 5;          // 0..15
    const int warpM = warp >> 2;        // 0..3
    const int warpN = warp & 3;         // 0..3

    // staging: thread covers one 16B chunk (row, qcol) in each of 4 arrays
    const int srow = tid >> 2;          // 0..127
    const int sq   = tid & 3;           // 0..3
    const uint32_t soff = (uint32_t)(srow * (SSTR * 4) + sq * 16);
    const __nv_bfloat16* pa = Ah + (size_t)(rowBase + srow) * K + sq * 8;
    const __nv_bfloat16* pl = Al + (size_t)(rowBase + srow) * K + sq * 8;
    const __nv_bfloat16* pw = Wh + (size_t)(colBase + srow) * K + sq * 8;
    const __nv_bfloat16* pv = Wl + (size_t)(colBase + srow) * K + sq * 8;

    auto stage = [&](int s, int k0) {
        const uint32_t base = sb + s * STAGE_BYTES;
        cp16(base + 0 * ARR_BYTES + soff, pa + k0);
        cp16(base + 1 * ARR_BYTES + soff, pl + k0);
        cp16(base + 2 * ARR_BYTES + soff, pw + k0);
        cp16(base + 3 * ARR_BYTES + soff, pv + k0);
        cp_commit();
    };

    const int ldrow = lane & 15;
    const uint32_t ldcol = ((uint32_t)(lane >> 4)) << 2;   // uint32 col 0 or 4
    const uint32_t aoff_base = (uint32_t)((warpM * 32 + ldrow) * (SSTR * 4)) + ldcol * 4;
    const uint32_t boff_base = (uint32_t)((warpN * 32 + ldrow) * (SSTR * 4)) + ldcol * 4;

    const int nt = K / 32;              // >= 16 always here
    stage(0, 0); stage(1, 32); stage(2, 64); stage(3, 96);

    for (int it = 0; it < nt; it++) {
        const int r = nt - 1 - it;
        if (r >= 3)      cp_wait<3>();
        else if (r == 2) cp_wait<2>();
        else if (r == 1) cp_wait<1>();
        else             cp_wait<0>();
        __syncthreads();
        if (it + 4 < nt) stage((it + 4) % NSTAGE, (it + 4) * 32);

        const uint32_t base = sb + (it % NSTAGE) * STAGE_BYTES;

        // ---- preload ALL fragments for this tile (both k-halves) ----
        uint32_t bhi[2][4][2], blo[2][4][2], ahh[2][2][4], alo[2][2][4];
#pragma unroll
        for (int kc = 0; kc < 2; kc++) {
            const uint32_t kko = (uint32_t)(kc * 8) * 4;    // uint32 offset *4B
#pragma unroll
            for (int p = 0; p < 2; p++) {
                uint32_t off = boff_base + (uint32_t)(p * 16 * SSTR * 4) + kko;
                uint32_t r0, r1, r2, r3;
                ldsm4(r0, r1, r2, r3, base + 2 * ARR_BYTES + off);
                bhi[kc][2 * p][0] = r0; bhi[kc][2 * p + 1][0] = r1;
                bhi[kc][2 * p][1] = r2; bhi[kc][2 * p + 1][1] = r3;
                ldsm4(r0, r1, r2, r3, base + 3 * ARR_BYTES + off);
                blo[kc][2 * p][0] = r0; blo[kc][2 * p + 1][0] = r1;
                blo[kc][2 * p][1] = r2; blo[kc][2 * p + 1][1] = r3;
            }
#pragma unroll
            for (int mi = 0; mi < 2; mi++) {
                uint32_t off = aoff_base + (uint32_t)(mi * 16 * SSTR * 4) + kko;
                ldsm4(ahh[kc][mi][0], ahh[kc][mi][1], ahh[kc][mi][2], ahh[kc][mi][3],
                      base + 0 * ARR_BYTES + off);
                ldsm4(alo[kc][mi][0], alo[kc][mi][1], alo[kc][mi][2], alo[kc][mi][3],
                      base + 1 * ARR_BYTES + off);
            }
        }

        // ---- 96 MMAs, term-major: acc reuse distance = 8 ----
#pragma unroll
        for (int kc = 0; kc < 2; kc++) {
#pragma unroll
            for (int mi = 0; mi < 2; mi++)
#pragma unroll
                for (int ni = 0; ni < 4; ni++)
                    mma_bf16(acc[mi][ni], ahh[kc][mi], bhi[kc][ni]);
#pragma unroll
            for (int mi = 0; mi < 2; mi++)
#pragma unroll
                for (int ni = 0; ni < 4; ni++)
                    mma_bf16(acc[mi][ni], ahh[kc][mi], blo[kc][ni]);
#pragma unroll
            for (int mi = 0; mi < 2; mi++)
#pragma unroll
                for (int ni = 0; ni < 4; ni++)
                    mma_bf16(acc[mi][ni], alo[kc][mi], bhi[kc][ni]);
        }
    }
}

// ---------------------------------------------------------------------------
// FFN first GEMM: t = silu(h @ W1^T + b1), bf16 hi/lo split output
// ---------------------------------------------------------------------------
template<int K, int N>
__global__ __launch_bounds__(NTHREADS, 1) void gemm_ffn1(
    const __nv_bfloat16* __restrict__ Ah, const __nv_bfloat16* __restrict__ Al,
    const __nv_bfloat16* __restrict__ Wh, const __nv_bfloat16* __restrict__ Wl,
    const float* __restrict__ bias,
    __nv_bfloat16* __restrict__ Ch, __nv_bfloat16* __restrict__ Cl)
{
    extern __shared__ __align__(128) uint32_t smem[];
    const uint32_t sb = (uint32_t)__cvta_generic_to_shared(smem);
    const int rowBase = blockIdx.y * 128;
    const int colBase = blockIdx.x * 128;

    float acc[2][4][4];
#pragma unroll
    for (int mi = 0; mi < 2; mi++)
#pragma unroll
        for (int ni = 0; ni < 4; ni++)
#pragma unroll
            for (int r = 0; r < 4; r++) acc[mi][ni][r] = 0.0f;

    gemm_mainloop<K>(Ah, Al, Wh, Wl, rowBase, colBase, sb, acc);

    const int lane = threadIdx.x & 31;
    const int warp = threadIdx.x >> 5;
    const int warpM = warp >> 2, warpN = warp & 3;
    const int g = lane >> 2, tg = lane & 3;
#pragma unroll
    for (int mi = 0; mi < 2; mi++) {
#pragma unroll
        for (int ni = 0; ni < 4; ni++) {
            int m0 = rowBase + warpM * 32 + mi * 16 + g;
            int n0 = colBase + warpN * 32 + ni * 8 + tg * 2;
            float bn0 = bias[n0], bn1 = bias[n0 + 1];
#pragma unroll
            for (int h = 0; h < 2; h++) {
                int m = m0 + h * 8;
                float u0 = silu_f(acc[mi][ni][2 * h + 0] + bn0);
                float u1 = silu_f(acc[mi][ni][2 * h + 1] + bn1);
                size_t idx = (size_t)m * N + n0;
                __nv_bfloat16 h0, l0, h1, l1;
                split_bf16(u0, h0, l0);
                split_bf16(u1, h1, l1);
                *(__nv_bfloat162*)(Ch + idx) = __halves2bfloat162(h0, h1);
                *(__nv_bfloat162*)(Cl + idx) = __halves2bfloat162(l0, l1);
            }
        }
    }
}

// ---------------------------------------------------------------------------
// FFN second GEMM: Q += t @ W2^T + b2  (residual, in place)
// ---------------------------------------------------------------------------
template<int K, int N>
__global__ __launch_bounds__(NTHREADS, 1) void gemm_ffn2(
    const __nv_bfloat16* __restrict__ Ah, const __nv_bfloat16* __restrict__ Al,
    const __nv_bfloat16* __restrict__ Wh, const __nv_bfloat16* __restrict__ Wl,
    const float* __restrict__ bias, float* __restrict__ C)
{
    extern __shared__ __align__(128) uint32_t smem[];
    const uint32_t sb = (uint32_t)__cvta_generic_to_shared(smem);
    const int rowBase = blockIdx.y * 128;
    const int colBase = blockIdx.x * 128;

    float acc[2][4][4];
#pragma unroll
    for (int mi = 0; mi < 2; mi++)
#pragma unroll
        for (int ni = 0; ni < 4; ni++)
#pragma unroll
            for (int r = 0; r < 4; r++) acc[mi][ni][r] = 0.0f;

    gemm_mainloop<K>(Ah, Al, Wh, Wl, rowBase, colBase, sb, acc);

    const int lane = threadIdx.x & 31;
    const int warp = threadIdx.x >> 5;
    const int warpM = warp >> 2, warpN = warp & 3;
    const int g = lane >> 2, tg = lane & 3;
#pragma unroll
    for (int mi = 0; mi < 2; mi++) {
#pragma unroll
        for (int ni = 0; ni < 4; ni++) {
            int m0 = rowBase + warpM * 32 + mi * 16 + g;
            int n0 = colBase + warpN * 32 + ni * 8 + tg * 2;
            float bn0 = bias[n0], bn1 = bias[n0 + 1];
#pragma unroll
            for (int h = 0; h < 2; h++) {
                int m = m0 + h * 8;
                size_t idx = (size_t)m * N + n0;
                C[idx]     = acc[mi][ni][2 * h + 0] + bn0 + C[idx];
                C[idx + 1] = acc[mi][ni][2 * h + 1] + bn1 + C[idx + 1];
            }
        }
    }
}

// ---------------------------------------------------------------------------
// Fused mu/sig GEMM + attention gather (H precomputed in g_H).
// W is the packed interleaved [1024, 512] matrix (even rows mu, odd rows sig)
// so each epilogue pair (n0, n0+1) = (mu, sig) for token n = n0/2. Epilogue:
//   mu = tanh(v0 + mu_b[n]); sg = v1 + sg_b[n]
//   Q[m,n] += sum_k exp(-0.5 (G[n,k]-mu)^2 / (sg^2+eps)) * H[m,n,k]
// ---------------------------------------------------------------------------
__global__ __launch_bounds__(NTHREADS, 1) void gemm_musig(
    const __nv_bfloat16* __restrict__ Ah, const __nv_bfloat16* __restrict__ Al,
    const __nv_bfloat16* __restrict__ Wh, const __nv_bfloat16* __restrict__ Wl,
    const float* __restrict__ mu_b, const float* __restrict__ sg_b,
    const float* __restrict__ G, float* __restrict__ Q)
{
    extern __shared__ __align__(128) uint32_t smem[];
    const uint32_t sb = (uint32_t)__cvta_generic_to_shared(smem);
    const int rowBase = blockIdx.y * 128;
    const int colBase = blockIdx.x * 128;

    float acc[2][4][4];
#pragma unroll
    for (int mi = 0; mi < 2; mi++)
#pragma unroll
        for (int ni = 0; ni < 4; ni++)
#pragma unroll
            for (int r = 0; r < 4; r++) acc[mi][ni][r] = 0.0f;

    gemm_mainloop<TDIM>(Ah, Al, Wh, Wl, rowBase, colBase, sb, acc);

    const int lane = threadIdx.x & 31;
    const int warp = threadIdx.x >> 5;
    const int warpM = warp >> 2, warpN = warp & 3;
    const int g = lane >> 2, tg = lane & 3;

#pragma unroll
    for (int ni = 0; ni < 4; ni++) {
        const int n0 = colBase + warpN * 32 + ni * 8 + tg * 2;   // even
        const int n  = n0 >> 1;
        const float bmu = mu_b[n], bsg = sg_b[n];
        const float4* G4 = (const float4*)(G + n * 8);
        const float4 gA = G4[0], gB = G4[1];
#pragma unroll
        for (int mi = 0; mi < 2; mi++) {
#pragma unroll
            for (int h = 0; h < 2; h++) {
                const int m = rowBase + warpM * 32 + mi * 16 + g + h * 8;
                const float muv = tanhf(acc[mi][ni][2 * h + 0] + bmu);
                const float sgv = acc[mi][ni][2 * h + 1] + bsg;
                const float rs  = 1.0f / fmaf(sgv, sgv, 1e-8f);
                const float4* H4 = (const float4*)(g_H + ((size_t)m * TDIM + n) * 8);
                const float4 hA = H4[0], hB = H4[1];
                float d, s = 0.0f;
                d = gA.x - muv; s += __expf(-0.5f * d * d * rs) * hA.x;
                d = gA.y - muv; s += __expf(-0.5f * d * d * rs) * hA.y;
                d = gA.z - muv; s += __expf(-0.5f * d * d * rs) * hA.z;
                d = gA.w - muv; s += __expf(-0.5f * d * d * rs) * hA.w;
                d = gB.x - muv; s += __expf(-0.5f * d * d * rs) * hB.x;
                d = gB.y - muv; s += __expf(-0.5f * d * d * rs) * hB.y;
                d = gB.z - muv; s += __expf(-0.5f * d * d * rs) * hB.z;
                d = gB.w - muv; s += __expf(-0.5f * d * d * rs) * hB.w;
                Q[(size_t)m * TDIM + n] += s;
            }
        }
    }
}

// ---------------------------------------------------------------------------
// One-shot weight split (+ mu/sig interleave pack): fp32 -> bf16 hi/lo
// ---------------------------------------------------------------------------
__global__ __launch_bounds__(256) void wsplit_all(
    const float* __restrict__ mu_w, const float* __restrict__ sg_w,
    const float* __restrict__ a_w1, const float* __restrict__ a_w2,
    const float* __restrict__ m_w1, const float* __restrict__ m_w2)
{
    size_t i = (size_t)blockIdx.x * 256 + threadIdx.x;
    float v;
    if (i < AW1_OFF) {
        // packed musig: per attn block 1024x512 (2^19 elems)
        size_t a   = i >> 19;
        size_t rem = i & 524287;
        size_t r   = rem >> 9;          // interleaved row 0..1023
        size_t k   = rem & 511;
        size_t src = a * 262144 + (r >> 1) * 512 + k;
        v = (r & 1) ? sg_w[src] : mu_w[src];
    } else if (i < AW2_OFF) v = a_w1[i - AW1_OFF];
    else if (i < MW1_OFF)   v = a_w2[i - AW2_OFF];
    else if (i < MW2_OFF)   v = m_w1[i - MW1_OFF];
    else                    v = m_w2[i - MW2_OFF];
    __nv_bfloat16 h, l;
    split_bf16(v, h, l);
    g_wh[i] = h; g_wl[i] = l;
}

// ---------------------------------------------------------------------------
// Prep: H[b,n,k] = cos(omega[n,k,:].x[b,:] + phase[n,k])  (once)
//       Q0[b,t]  = silu(x[b,:].l1_w[t,:] + l1_b[t])
// ---------------------------------------------------------------------------
__global__ __launch_bounds__(256) void prep_kernel(
    const float* __restrict__ x, const float* __restrict__ omega,
    const float* __restrict__ phase, const float* __restrict__ l1_w,
    const float* __restrict__ l1_b)
{
    int idx = blockIdx.x * 256 + threadIdx.x;     // b*T + n
    int b = idx >> 9, n = idx & 511;
    float x0 = x[b * 2 + 0], x1 = x[b * 2 + 1];
    float out[8];
#pragma unroll
    for (int k = 0; k < 8; k++) {
        int nk = n * 8 + k;
        float arg = fmaf(omega[nk * 2 + 0], x0,
                    fmaf(omega[nk * 2 + 1], x1, phase[nk]));
        out[k] = cosf(arg);
    }
    float4* H4 = (float4*)(g_H + (size_t)idx * 8);
    H4[0] = make_float4(out[0], out[1], out[2], out[3]);
    H4[1] = make_float4(out[4], out[5], out[6], out[7]);

    float p = fmaf(x0, l1_w[n * 2 + 0], fmaf(x1, l1_w[n * 2 + 1], l1_b[n]));
    g_Q[idx] = silu_f(p);
}

// ---------------------------------------------------------------------------
// LayerNorm over T=512, one warp per row; outputs bf16 hi/lo split
// ---------------------------------------------------------------------------
__global__ __launch_bounds__(256) void ln_kernel(
    const float* __restrict__ X, const float* __restrict__ gam,
    const float* __restrict__ bet)
{
    int warp = threadIdx.x >> 5, lane = threadIdx.x & 31;
    int row = blockIdx.x * 8 + warp;
    const float4* xr = (const float4*)(X + (size_t)row * 512);
    float4 v[4];
    float s = 0.0f;
#pragma unroll
    for (int j = 0; j < 4; j++) {
        v[j] = xr[lane + j * 32];
        s += v[j].x + v[j].y + v[j].z + v[j].w;
    }
#pragma unroll
    for (int o = 16; o > 0; o >>= 1) s += __shfl_xor_sync(0xffffffffu, s, o);
    float m = s * (1.0f / 512.0f);
    float vs = 0.0f;
#pragma unroll
    for (int j = 0; j < 4; j++) {
        float dx = v[j].x - m, dy = v[j].y - m, dz = v[j].z - m, dw = v[j].w - m;
        vs += dx * dx + dy * dy + dz * dz + dw * dw;
    }
#pragma unroll
    for (int o = 16; o > 0; o >>= 1) vs += __shfl_xor_sync(0xffffffffu, vs, o);
    float inv = rsqrtf(vs * (1.0f / 512.0f) + 1e-5f);

    __nv_bfloat162* yh = (__nv_bfloat162*)(g_hh + (size_t)row * 512);
    __nv_bfloat162* yl = (__nv_bfloat162*)(g_hl + (size_t)row * 512);
    const float4* gr = (const float4*)gam;
    const float4* br = (const float4*)bet;
#pragma unroll
    for (int j = 0; j < 4; j++) {
        int c = lane + j * 32;
        float4 gg = gr[c], bb = br[c];
        float o0 = (v[j].x - m) * inv * gg.x + bb.x;
        float o1 = (v[j].y - m) * inv * gg.y + bb.y;
        float o2 = (v[j].z - m) * inv * gg.z + bb.z;
        float o3 = (v[j].w - m) * inv * gg.w + bb.w;
        __nv_bfloat16 h0, l0, h1, l1, h2, l2, h3, l3;
        split_bf16(o0, h0, l0); split_bf16(o1, h1, l1);
        split_bf16(o2, h2, l2); split_bf16(o3, h3, l3);
        yh[c * 2    ] = __halves2bfloat162(h0, h1);
        yh[c * 2 + 1] = __halves2bfloat162(h2, h3);
        yl[c * 2    ] = __halves2bfloat162(l0, l1);
        yl[c * 2 + 1] = __halves2bfloat162(l2, l3);
    }
}

// ---------------------------------------------------------------------------
// Readout: out[b] = sum_t silu(Q[b,t]) * ro_w[t] + ro_b
// ---------------------------------------------------------------------------
__global__ __launch_bounds__(256) void final_kernel(
    const float* __restrict__ ro_w, const float* __restrict__ ro_b,
    float* __restrict__ out)
{
    int warp = threadIdx.x >> 5, lane = threadIdx.x & 31;
    int row = blockIdx.x * 8 + warp;
    const float4* q4 = (const float4*)(g_Q + (size_t)row * 512);
    const float4* w4 = (const float4*)ro_w;
    float s = 0.0f;
#pragma unroll
    for (int j = 0; j < 4; j++) {
        int c = lane + j * 32;
        float4 q = q4[c], w = w4[c];
        s += silu_f(q.x) * w.x + silu_f(q.y) * w.y
           + silu_f(q.z) * w.z + silu_f(q.w) * w.w;
    }
#pragma unroll
    for (int o = 16; o > 0; o >>= 1) s += __shfl_xor_sync(0xffffffffu, s, o);
    if (lane == 0) out[row] = s + ro_b[0];
}

// ---------------------------------------------------------------------------
// Host launcher
// ---------------------------------------------------------------------------
extern "C" void kernel_launch(void* const* d_in, const int* in_sizes, int n_in,
                              void* d_out, int out_size)
{
    const float* x      = (const float*)d_in[0];
    const float* omega  = (const float*)d_in[1];
    const float* G      = (const float*)d_in[2];
    const float* phase  = (const float*)d_in[3];
    const float* l1_w   = (const float*)d_in[4];
    const float* l1_b   = (const float*)d_in[5];
    const float* mu_w   = (const float*)d_in[6];
    const float* mu_b   = (const float*)d_in[7];
    const float* sg_w   = (const float*)d_in[8];
    const float* sg_b   = (const float*)d_in[9];
    const float* alnqg  = (const float*)d_in[10];
    const float* alnqb  = (const float*)d_in[11];
    const float* alnfg  = (const float*)d_in[12];
    const float* alnfb  = (const float*)d_in[13];
    const float* a_w1   = (const float*)d_in[14];
    const float* a_b1   = (const float*)d_in[15];
    const float* a_w2   = (const float*)d_in[16];
    const float* a_b2   = (const float*)d_in[17];
    const float* mln_g  = (const float*)d_in[18];
    const float* mln_b  = (const float*)d_in[19];
    const float* m_w1   = (const float*)d_in[20];
    const float* m_b1   = (const float*)d_in[21];
    const float* m_w2   = (const float*)d_in[22];
    const float* m_b2   = (const float*)d_in[23];
    const float* ro_w   = (const float*)d_in[24];
    const float* ro_b   = (const float*)d_in[25];
    float* out = (float*)d_out;

    __nv_bfloat16* wh; __nv_bfloat16* wl;
    float* Q;
    __nv_bfloat16* hh; __nv_bfloat16* hl;
    __nv_bfloat16* th; __nv_bfloat16* tl;
    {
        void* p;
        cudaGetSymbolAddress(&p, g_wh); wh = (__nv_bfloat16*)p;
        cudaGetSymbolAddress(&p, g_wl); wl = (__nv_bfloat16*)p;
        cudaGetSymbolAddress(&p, g_Q);  Q  = (float*)p;
        cudaGetSymbolAddress(&p, g_hh); hh = (__nv_bfloat16*)p;
        cudaGetSymbolAddress(&p, g_hl); hl = (__nv_bfloat16*)p;
        cudaGetSymbolAddress(&p, g_th); th = (__nv_bfloat16*)p;
        cudaGetSymbolAddress(&p, g_tl); tl = (__nv_bfloat16*)p;
    }

    cudaFuncSetAttribute(gemm_musig,
                         cudaFuncAttributeMaxDynamicSharedMemorySize, SMEM_BYTES);
    cudaFuncSetAttribute(gemm_ffn1<TDIM, FDIM>,
                         cudaFuncAttributeMaxDynamicSharedMemorySize, SMEM_BYTES);
    cudaFuncSetAttribute(gemm_ffn2<FDIM, TDIM>,
                         cudaFuncAttributeMaxDynamicSharedMemorySize, SMEM_BYTES);

    const int ew_blocks = (BATCH * TDIM) / 256;   // 16384
    const dim3 g_ms(1024 / 128, BATCH / 128);     // (8, 64)
    const dim3 g_f1(FDIM / 128, BATCH / 128);     // (16, 64)
    const dim3 g_f2(TDIM / 128, BATCH / 128);     // (4, 64)

    wsplit_all<<<WTOTAL / 256, 256>>>(mu_w, sg_w, a_w1, a_w2, m_w1, m_w2);
    prep_kernel<<<ew_blocks, 256>>>(x, omega, phase, l1_w, l1_b);

    for (int i = 0; i < NATTN; i++) {
        const size_t wms = (size_t)i * 1024 * 512;
        const size_t wft = (size_t)i * FDIM * TDIM;
        ln_kernel<<<BATCH / 8, 256>>>(Q, alnqg + i * TDIM, alnqb + i * TDIM);
        gemm_musig<<<g_ms, NTHREADS, SMEM_BYTES>>>(
            hh, hl, wh + MS_OFF + wms, wl + MS_OFF + wms,
            mu_b + i * TDIM, sg_b + i * TDIM, G, Q);
        ln_kernel<<<BATCH / 8, 256>>>(Q, alnfg + i * TDIM, alnfb + i * TDIM);
        gemm_ffn1<TDIM, FDIM><<<g_f1, NTHREADS, SMEM_BYTES>>>(
            hh, hl, wh + AW1_OFF + wft, wl + AW1_OFF + wft,
            a_b1 + i * FDIM, th, tl);
        gemm_ffn2<FDIM, TDIM><<<g_f2, NTHREADS, SMEM_BYTES>>>(
            th, tl, wh + AW2_OFF + wft, wl + AW2_OFF + wft,
            a_b2 + i * TDIM, Q);
    }
    for (int i = 0; i < NMLP; i++) {
        const size_t wft = (size_t)i * FDIM * TDIM;
        ln_kernel<<<BATCH / 8, 256>>>(Q, mln_g + i * TDIM, mln_b + i * TDIM);
        gemm_ffn1<TDIM, FDIM><<<g_f1, NTHREADS, SMEM_BYTES>>>(
            hh, hl, wh + MW1_OFF + wft, wl + MW1_OFF + wft,
            m_b1 + i * FDIM, th, tl);
        gemm_ffn2<FDIM, TDIM><<<g_f2, NTHREADS, SMEM_BYTES>>>(
            th, tl, wh + MW2_OFF + wft, wl + MW2_OFF + wft,
            m_b2 + i * TDIM, Q);
    }
    final_kernel<<<BATCH / 8, 256>>>(ro_w, ro_b, out);
}

// round 10
// speedup vs baseline: 1.2090x; 1.2090x over previous
#include <cuda_runtime.h>
#include <cuda_bf16.h>
#include <cstdint>
#include <math.h>

// ---------------------------------------------------------------------------
// Problem constants
// ---------------------------------------------------------------------------
#define BATCH 8192
#define TDIM  512
#define FDIM  2048
#define NATTN 4
#define NMLP  2

// weight scratch layout (element offsets into g_wh / g_wl)
// [MS_OFF)  : packed mu/sig, per attn block 1024x512, rows interleaved
//             (even row r -> mu_w[r/2], odd row r -> sg_w[r/2])
#define MS_OFF  0
#define AW1_OFF 2097152
#define AW2_OFF 6291456
#define MW1_OFF 10485760
#define MW2_OFF 12582912
#define WTOTAL  14680064

// ---------------------------------------------------------------------------
// Device scratch (static — no allocation at launch time)
// ---------------------------------------------------------------------------
__device__ __nv_bfloat16 g_wh[WTOTAL];          // 29 MB  weight hi
__device__ __nv_bfloat16 g_wl[WTOTAL];          // 29 MB  weight lo
__device__ float         g_Q [BATCH * TDIM];    // 16 MB  residual stream
__device__ float         g_H [BATCH * TDIM * 8];// 128 MB RFF tokens (precomputed)
__device__ __nv_bfloat16 g_hh[BATCH * TDIM];    // LN output hi
__device__ __nv_bfloat16 g_hl[BATCH * TDIM];    // LN output lo
__device__ __nv_bfloat16 g_th[BATCH * FDIM];    // FFN mid hi
__device__ __nv_bfloat16 g_tl[BATCH * FDIM];    // FFN mid lo

// ---------------------------------------------------------------------------
// Helpers
// ---------------------------------------------------------------------------
__device__ __forceinline__ float silu_f(float x) {
    return x / (1.0f + __expf(-x));
}

__device__ __forceinline__ void split_bf16(float x, __nv_bfloat16& hi, __nv_bfloat16& lo) {
    hi = __float2bfloat16_rn(x);
    lo = __float2bfloat16_rn(x - __bfloat162float(hi));
}

__device__ __forceinline__ void mma_bf16(float* d, const uint32_t* a, const uint32_t* b) {
    asm volatile(
        "mma.sync.aligned.m16n8k16.row.col.f32.bf16.bf16.f32 "
        "{%0,%1,%2,%3}, {%4,%5,%6,%7}, {%8,%9}, {%0,%1,%2,%3};\n"
        : "+f"(d[0]), "+f"(d[1]), "+f"(d[2]), "+f"(d[3])
        : "r"(a[0]), "r"(a[1]), "r"(a[2]), "r"(a[3]), "r"(b[0]), "r"(b[1]));
}

__device__ __forceinline__ void cp16(uint32_t dst, const void* src) {
    asm volatile("cp.async.cg.shared.global [%0], [%1], 16;\n" :: "r"(dst), "l"(src));
}
__device__ __forceinline__ void cp_commit() {
    asm volatile("cp.async.commit_group;\n");
}
template<int N> __device__ __forceinline__ void cp_wait() {
    asm volatile("cp.async.wait_group %0;\n" :: "n"(N));
}

__device__ __forceinline__ void ldsm4(uint32_t& r0, uint32_t& r1, uint32_t& r2,
                                      uint32_t& r3, uint32_t addr) {
    asm volatile("ldmatrix.sync.aligned.m8n8.x4.shared.b16 {%0,%1,%2,%3}, [%4];\n"
                 : "=r"(r0), "=r"(r1), "=r"(r2), "=r"(r3) : "r"(addr));
}

// XOR-swizzled smem layout: per array, row r (0..127) holds 32 bf16 = 64B =
// 4 chunks of 16B; logical chunk c lives at physical chunk c ^ ((r>>1)&3).
// ldmatrix phase check (8 lanes = 8 consecutive rows, fixed c): banks
// 16r + 4*(c^((r>>1)&3)) mod 32 cover all 32 banks exactly -> conflict-free.
// Staging check: a warp writes 8 rows x 4 chunks = every bank once.
__device__ __forceinline__ uint32_t swz(int r, int c) {
    return (uint32_t)(r * 64 + ((c ^ ((r >> 1) & 3)) * 16));
}

// ---------------------------------------------------------------------------
// GEMM mainloop (bf16x3 split): R8 config — 256 threads, 2 CTA/SM,
// warp grid 2m x 4n, warp tile 64x32 (traffic-optimal) — PLUS:
//   * unpadded XOR-swizzled layout: stage 40KB -> 32KB
//   * 3-stage cp.async ring (96KB/CTA, fits 2 CTAs/SM)
//   * ONE __syncthreads per K-tile (restaged buffer last read a full
//     iteration ago), prefetch distance 2 (wait<1> w/ 2 groups in flight)
//   acc += Ah*Wh + Ah*Wl + Al*Wh; term-major MMA order (reuse distance 4).
// ---------------------------------------------------------------------------
#define ARR_BYTES   (128 * 64)         // 8192
#define STAGE_BYTES (4 * ARR_BYTES)    // 32768: Ahi, Alo, Whi, Wlo
#define NSTAGE 3
#define SMEM_BYTES  (NSTAGE * STAGE_BYTES)  // 98304
#define NTHREADS 256

template<int K>
__device__ __forceinline__ void gemm_mainloop(
    const __nv_bfloat16* __restrict__ Ah, const __nv_bfloat16* __restrict__ Al,
    const __nv_bfloat16* __restrict__ Wh, const __nv_bfloat16* __restrict__ Wl,
    int rowBase, int colBase, uint32_t sb, float acc[4][4][4])
{
    const int tid  = threadIdx.x;
    const int lane = tid & 31;
    const int warp = tid >> 5;
    const int warpM = warp & 1;
    const int warpN = warp >> 1;

    // staging: thread covers 16B chunks tid and tid+256 of each array
    const int r0s = tid >> 2,        q0s = tid & 3;
    const int r1s = (tid + 256) >> 2, q1s = tid & 3;   // same q, rows +64
    const uint32_t off0 = swz(r0s, q0s);
    const uint32_t off1 = swz(r1s, q1s);
    const __nv_bfloat16* a0 = Ah + (size_t)(rowBase + r0s) * K + q0s * 8;
    const __nv_bfloat16* l0 = Al + (size_t)(rowBase + r0s) * K + q0s * 8;
    const __nv_bfloat16* w0 = Wh + (size_t)(colBase + r0s) * K + q0s * 8;
    const __nv_bfloat16* v0 = Wl + (size_t)(colBase + r0s) * K + q0s * 8;
    const __nv_bfloat16* a1 = Ah + (size_t)(rowBase + r1s) * K + q1s * 8;
    const __nv_bfloat16* l1 = Al + (size_t)(rowBase + r1s) * K + q1s * 8;
    const __nv_bfloat16* w1 = Wh + (size_t)(colBase + r1s) * K + q1s * 8;
    const __nv_bfloat16* v1 = Wl + (size_t)(colBase + r1s) * K + q1s * 8;

    auto stage = [&](int s, int k0) {
        const uint32_t base = sb + s * STAGE_BYTES;
        cp16(base + 0 * ARR_BYTES + off0, a0 + k0);
        cp16(base + 1 * ARR_BYTES + off0, l0 + k0);
        cp16(base + 2 * ARR_BYTES + off0, w0 + k0);
        cp16(base + 3 * ARR_BYTES + off0, v0 + k0);
        cp16(base + 0 * ARR_BYTES + off1, a1 + k0);
        cp16(base + 1 * ARR_BYTES + off1, l1 + k0);
        cp16(base + 2 * ARR_BYTES + off1, w1 + k0);
        cp16(base + 3 * ARR_BYTES + off1, v1 + k0);
        cp_commit();
    };

    // fragment load offsets (precomputed; khalf = 16B column within k-chunk)
    const int ldrow = lane & 15;
    const int khalf = lane >> 4;                 // 0 or 1
    uint32_t offA[2][4], offB[2][2];
#pragma unroll
    for (int kc = 0; kc < 2; kc++) {
        const int c = kc * 2 + khalf;
#pragma unroll
        for (int mi = 0; mi < 4; mi++)
            offA[kc][mi] = swz(warpM * 64 + mi * 16 + ldrow, c);
#pragma unroll
        for (int p = 0; p < 2; p++)
            offB[kc][p]  = swz(warpN * 32 + p * 16 + ldrow, c);
    }

    const int nt = K / 32;                       // >= 16
    stage(0, 0);
    stage(1, 32);

    for (int it = 0; it < nt; it++) {
        if (it < nt - 1) cp_wait<1>(); else cp_wait<0>();
        __syncthreads();
        if (it + 2 < nt) stage((it + 2) % NSTAGE, (it + 2) * 32);

        const uint32_t base = sb + (it % NSTAGE) * STAGE_BYTES;
#pragma unroll
        for (int kc = 0; kc < 2; kc++) {
            uint32_t bhi[4][2], blo[4][2];
#pragma unroll
            for (int p = 0; p < 2; p++) {
                uint32_t r0, r1, r2, r3;
                ldsm4(r0, r1, r2, r3, base + 2 * ARR_BYTES + offB[kc][p]);
                bhi[2 * p][0] = r0; bhi[2 * p + 1][0] = r1;
                bhi[2 * p][1] = r2; bhi[2 * p + 1][1] = r3;
                ldsm4(r0, r1, r2, r3, base + 3 * ARR_BYTES + offB[kc][p]);
                blo[2 * p][0] = r0; blo[2 * p + 1][0] = r1;
                blo[2 * p][1] = r2; blo[2 * p + 1][1] = r3;
            }
#pragma unroll
            for (int mi = 0; mi < 4; mi++) {
                uint32_t ah[4], al[4];
                ldsm4(ah[0], ah[1], ah[2], ah[3], base + 0 * ARR_BYTES + offA[kc][mi]);
                ldsm4(al[0], al[1], al[2], al[3], base + 1 * ARR_BYTES + offA[kc][mi]);
                // term-major: 4 independent MMAs between acc reuses
#pragma unroll
                for (int ni = 0; ni < 4; ni++) mma_bf16(acc[mi][ni], ah, bhi[ni]);
#pragma unroll
                for (int ni = 0; ni < 4; ni++) mma_bf16(acc[mi][ni], ah, blo[ni]);
#pragma unroll
                for (int ni = 0; ni < 4; ni++) mma_bf16(acc[mi][ni], al, bhi[ni]);
            }
        }
    }
}

// ---------------------------------------------------------------------------
// FFN first GEMM: t = silu(h @ W1^T + b1), bf16 hi/lo split output
// ---------------------------------------------------------------------------
template<int K, int N>
__global__ __launch_bounds__(NTHREADS, 2) void gemm_ffn1(
    const __nv_bfloat16* __restrict__ Ah, const __nv_bfloat16* __restrict__ Al,
    const __nv_bfloat16* __restrict__ Wh, const __nv_bfloat16* __restrict__ Wl,
    const float* __restrict__ bias,
    __nv_bfloat16* __restrict__ Ch, __nv_bfloat16* __restrict__ Cl)
{
    extern __shared__ __align__(128) uint32_t smem[];
    const uint32_t sb = (uint32_t)__cvta_generic_to_shared(smem);
    const int rowBase = blockIdx.y * 128;
    const int colBase = blockIdx.x * 128;

    float acc[4][4][4];
#pragma unroll
    for (int mi = 0; mi < 4; mi++)
#pragma unroll
        for (int ni = 0; ni < 4; ni++)
#pragma unroll
            for (int r = 0; r < 4; r++) acc[mi][ni][r] = 0.0f;

    gemm_mainloop<K>(Ah, Al, Wh, Wl, rowBase, colBase, sb, acc);

    const int lane = threadIdx.x & 31;
    const int warp = threadIdx.x >> 5;
    const int warpM = warp & 1, warpN = warp >> 1;
    const int g = lane >> 2, tg = lane & 3;
#pragma unroll
    for (int mi = 0; mi < 4; mi++) {
#pragma unroll
        for (int ni = 0; ni < 4; ni++) {
            int m0 = rowBase + warpM * 64 + mi * 16 + g;
            int n0 = colBase + warpN * 32 + ni * 8 + tg * 2;
            float bn0 = bias[n0], bn1 = bias[n0 + 1];
#pragma unroll
            for (int h = 0; h < 2; h++) {
                int m = m0 + h * 8;
                float u0 = silu_f(acc[mi][ni][2 * h + 0] + bn0);
                float u1 = silu_f(acc[mi][ni][2 * h + 1] + bn1);
                size_t idx = (size_t)m * N + n0;
                __nv_bfloat16 h0, l0, h1, l1;
                split_bf16(u0, h0, l0);
                split_bf16(u1, h1, l1);
                *(__nv_bfloat162*)(Ch + idx) = __halves2bfloat162(h0, h1);
                *(__nv_bfloat162*)(Cl + idx) = __halves2bfloat162(l0, l1);
            }
        }
    }
}

// ---------------------------------------------------------------------------
// FFN second GEMM: Q += t @ W2^T + b2  (residual, in place)
// ---------------------------------------------------------------------------
template<int K, int N>
__global__ __launch_bounds__(NTHREADS, 2) void gemm_ffn2(
    const __nv_bfloat16* __restrict__ Ah, const __nv_bfloat16* __restrict__ Al,
    const __nv_bfloat16* __restrict__ Wh, const __nv_bfloat16* __restrict__ Wl,
    const float* __restrict__ bias, float* __restrict__ C)
{
    extern __shared__ __align__(128) uint32_t smem[];
    const uint32_t sb = (uint32_t)__cvta_generic_to_shared(smem);
    const int rowBase = blockIdx.y * 128;
    const int colBase = blockIdx.x * 128;

    float acc[4][4][4];
#pragma unroll
    for (int mi = 0; mi < 4; mi++)
#pragma unroll
        for (int ni = 0; ni < 4; ni++)
#pragma unroll
            for (int r = 0; r < 4; r++) acc[mi][ni][r] = 0.0f;

    gemm_mainloop<K>(Ah, Al, Wh, Wl, rowBase, colBase, sb, acc);

    const int lane = threadIdx.x & 31;
    const int warp = threadIdx.x >> 5;
    const int warpM = warp & 1, warpN = warp >> 1;
    const int g = lane >> 2, tg = lane & 3;
#pragma unroll
    for (int mi = 0; mi < 4; mi++) {
#pragma unroll
        for (int ni = 0; ni < 4; ni++) {
            int m0 = rowBase + warpM * 64 + mi * 16 + g;
            int n0 = colBase + warpN * 32 + ni * 8 + tg * 2;
            float bn0 = bias[n0], bn1 = bias[n0 + 1];
#pragma unroll
            for (int h = 0; h < 2; h++) {
                int m = m0 + h * 8;
                size_t idx = (size_t)m * N + n0;
                C[idx]     = acc[mi][ni][2 * h + 0] + bn0 + C[idx];
                C[idx + 1] = acc[mi][ni][2 * h + 1] + bn1 + C[idx + 1];
            }
        }
    }
}

// ---------------------------------------------------------------------------
// Fused mu/sig GEMM + attention gather (H precomputed in g_H).
// W is the packed interleaved [1024, 512] matrix (even rows mu, odd rows sig)
// so each epilogue pair (n0, n0+1) = (mu, sig) for token n = n0/2. Epilogue:
//   mu = tanh(v0 + mu_b[n]); sg = v1 + sg_b[n]
//   Q[m,n] += sum_k exp(-0.5 (G[n,k]-mu)^2 / (sg^2+eps)) * H[m,n,k]
// ---------------------------------------------------------------------------
__global__ __launch_bounds__(NTHREADS, 2) void gemm_musig(
    const __nv_bfloat16* __restrict__ Ah, const __nv_bfloat16* __restrict__ Al,
    const __nv_bfloat16* __restrict__ Wh, const __nv_bfloat16* __restrict__ Wl,
    const float* __restrict__ mu_b, const float* __restrict__ sg_b,
    const float* __restrict__ G, float* __restrict__ Q)
{
    extern __shared__ __align__(128) uint32_t smem[];
    const uint32_t sb = (uint32_t)__cvta_generic_to_shared(smem);
    const int rowBase = blockIdx.y * 128;
    const int colBase = blockIdx.x * 128;

    float acc[4][4][4];
#pragma unroll
    for (int mi = 0; mi < 4; mi++)
#pragma unroll
        for (int ni = 0; ni < 4; ni++)
#pragma unroll
            for (int r = 0; r < 4; r++) acc[mi][ni][r] = 0.0f;

    gemm_mainloop<TDIM>(Ah, Al, Wh, Wl, rowBase, colBase, sb, acc);

    const int lane = threadIdx.x & 31;
    const int warp = threadIdx.x >> 5;
    const int warpM = warp & 1, warpN = warp >> 1;
    const int g = lane >> 2, tg = lane & 3;

#pragma unroll
    for (int ni = 0; ni < 4; ni++) {
        const int n0 = colBase + warpN * 32 + ni * 8 + tg * 2;   // even
        const int n  = n0 >> 1;
        const float bmu = mu_b[n], bsg = sg_b[n];
        const float4* G4 = (const float4*)(G + n * 8);
        const float4 gA = G4[0], gB = G4[1];
#pragma unroll
        for (int mi = 0; mi < 4; mi++) {
#pragma unroll
            for (int h = 0; h < 2; h++) {
                const int m = rowBase + warpM * 64 + mi * 16 + g + h * 8;
                const float muv = tanhf(acc[mi][ni][2 * h + 0] + bmu);
                const float sgv = acc[mi][ni][2 * h + 1] + bsg;
                const float rs  = 1.0f / fmaf(sgv, sgv, 1e-8f);
                const float4* H4 = (const float4*)(g_H + ((size_t)m * TDIM + n) * 8);
                const float4 hA = H4[0], hB = H4[1];
                float d, s = 0.0f;
                d = gA.x - muv; s += __expf(-0.5f * d * d * rs) * hA.x;
                d = gA.y - muv; s += __expf(-0.5f * d * d * rs) * hA.y;
                d = gA.z - muv; s += __expf(-0.5f * d * d * rs) * hA.z;
                d = gA.w - muv; s += __expf(-0.5f * d * d * rs) * hA.w;
                d = gB.x - muv; s += __expf(-0.5f * d * d * rs) * hB.x;
                d = gB.y - muv; s += __expf(-0.5f * d * d * rs) * hB.y;
                d = gB.z - muv; s += __expf(-0.5f * d * d * rs) * hB.z;
                d = gB.w - muv; s += __expf(-0.5f * d * d * rs) * hB.w;
                Q[(size_t)m * TDIM + n] += s;
            }
        }
    }
}

// ---------------------------------------------------------------------------
// One-shot weight split (+ mu/sig interleave pack): fp32 -> bf16 hi/lo
// ---------------------------------------------------------------------------
__global__ __launch_bounds__(256) void wsplit_all(
    const float* __restrict__ mu_w, const float* __restrict__ sg_w,
    const float* __restrict__ a_w1, const float* __restrict__ a_w2,
    const float* __restrict__ m_w1, const float* __restrict__ m_w2)
{
    size_t i = (size_t)blockIdx.x * 256 + threadIdx.x;
    float v;
    if (i < AW1_OFF) {
        // packed musig: per attn block 1024x512 (2^19 elems)
        size_t a   = i >> 19;
        size_t rem = i & 524287;
        size_t r   = rem >> 9;          // interleaved row 0..1023
        size_t k   = rem & 511;
        size_t src = a * 262144 + (r >> 1) * 512 + k;
        v = (r & 1) ? sg_w[src] : mu_w[src];
    } else if (i < AW2_OFF) v = a_w1[i - AW1_OFF];
    else if (i < MW1_OFF)   v = a_w2[i - AW2_OFF];
    else if (i < MW2_OFF)   v = m_w1[i - MW1_OFF];
    else                    v = m_w2[i - MW2_OFF];
    __nv_bfloat16 h, l;
    split_bf16(v, h, l);
    g_wh[i] = h; g_wl[i] = l;
}

// ---------------------------------------------------------------------------
// Prep: H[b,n,k] = cos(omega[n,k,:].x[b,:] + phase[n,k])  (once)
//       Q0[b,t]  = silu(x[b,:].l1_w[t,:] + l1_b[t])
// ---------------------------------------------------------------------------
__global__ __launch_bounds__(256) void prep_kernel(
    const float* __restrict__ x, const float* __restrict__ omega,
    const float* __restrict__ phase, const float* __restrict__ l1_w,
    const float* __restrict__ l1_b)
{
    int idx = blockIdx.x * 256 + threadIdx.x;     // b*T + n
    int b = idx >> 9, n = idx & 511;
    float x0 = x[b * 2 + 0], x1 = x[b * 2 + 1];
    float out[8];
#pragma unroll
    for (int k = 0; k < 8; k++) {
        int nk = n * 8 + k;
        float arg = fmaf(omega[nk * 2 + 0], x0,
                    fmaf(omega[nk * 2 + 1], x1, phase[nk]));
        out[k] = cosf(arg);
    }
    float4* H4 = (float4*)(g_H + (size_t)idx * 8);
    H4[0] = make_float4(out[0], out[1], out[2], out[3]);
    H4[1] = make_float4(out[4], out[5], out[6], out[7]);

    float p = fmaf(x0, l1_w[n * 2 + 0], fmaf(x1, l1_w[n * 2 + 1], l1_b[n]));
    g_Q[idx] = silu_f(p);
}

// ---------------------------------------------------------------------------
// LayerNorm over T=512, one warp per row; outputs bf16 hi/lo split
// ---------------------------------------------------------------------------
__global__ __launch_bounds__(256) void ln_kernel(
    const float* __restrict__ X, const float* __restrict__ gam,
    const float* __restrict__ bet)
{
    int warp = threadIdx.x >> 5, lane = threadIdx.x & 31;
    int row = blockIdx.x * 8 + warp;
    const float4* xr = (const float4*)(X + (size_t)row * 512);
    float4 v[4];
    float s = 0.0f;
#pragma unroll
    for (int j = 0; j < 4; j++) {
        v[j] = xr[lane + j * 32];
        s += v[j].x + v[j].y + v[j].z + v[j].w;
    }
#pragma unroll
    for (int o = 16; o > 0; o >>= 1) s += __shfl_xor_sync(0xffffffffu, s, o);
    float m = s * (1.0f / 512.0f);
    float vs = 0.0f;
#pragma unroll
    for (int j = 0; j < 4; j++) {
        float dx = v[j].x - m, dy = v[j].y - m, dz = v[j].z - m, dw = v[j].w - m;
        vs += dx * dx + dy * dy + dz * dz + dw * dw;
    }
#pragma unroll
    for (int o = 16; o > 0; o >>= 1) vs += __shfl_xor_sync(0xffffffffu, vs, o);
    float inv = rsqrtf(vs * (1.0f / 512.0f) + 1e-5f);

    __nv_bfloat162* yh = (__nv_bfloat162*)(g_hh + (size_t)row * 512);
    __nv_bfloat162* yl = (__nv_bfloat162*)(g_hl + (size_t)row * 512);
    const float4* gr = (const float4*)gam;
    const float4* br = (const float4*)bet;
#pragma unroll
    for (int j = 0; j < 4; j++) {
        int c = lane + j * 32;
        float4 gg = gr[c], bb = br[c];
        float o0 = (v[j].x - m) * inv * gg.x + bb.x;
        float o1 = (v[j].y - m) * inv * gg.y + bb.y;
        float o2 = (v[j].z - m) * inv * gg.z + bb.z;
        float o3 = (v[j].w - m) * inv * gg.w + bb.w;
        __nv_bfloat16 h0, l0, h1, l1, h2, l2, h3, l3;
        split_bf16(o0, h0, l0); split_bf16(o1, h1, l1);
        split_bf16(o2, h2, l2); split_bf16(o3, h3, l3);
        yh[c * 2    ] = __halves2bfloat162(h0, h1);
        yh[c * 2 + 1] = __halves2bfloat162(h2, h3);
        yl[c * 2    ] = __halves2bfloat162(l0, l1);
        yl[c * 2 + 1] = __halves2bfloat162(l2, l3);
    }
}

// ---------------------------------------------------------------------------
// Readout: out[b] = sum_t silu(Q[b,t]) * ro_w[t] + ro_b
// ---------------------------------------------------------------------------
__global__ __launch_bounds__(256) void final_kernel(
    const float* __restrict__ ro_w, const float* __restrict__ ro_b,
    float* __restrict__ out)
{
    int warp = threadIdx.x >> 5, lane = threadIdx.x & 31;
    int row = blockIdx.x * 8 + warp;
    const float4* q4 = (const float4*)(g_Q + (size_t)row * 512);
    const float4* w4 = (const float4*)ro_w;
    float s = 0.0f;
#pragma unroll
    for (int j = 0; j < 4; j++) {
        int c = lane + j * 32;
        float4 q = q4[c], w = w4[c];
        s += silu_f(q.x) * w.x + silu_f(q.y) * w.y
           + silu_f(q.z) * w.z + silu_f(q.w) * w.w;
    }
#pragma unroll
    for (int o = 16; o > 0; o >>= 1) s += __shfl_xor_sync(0xffffffffu, s, o);
    if (lane == 0) out[row] = s + ro_b[0];
}

// ---------------------------------------------------------------------------
// Host launcher
// ---------------------------------------------------------------------------
extern "C" void kernel_launch(void* const* d_in, const int* in_sizes, int n_in,
                              void* d_out, int out_size)
{
    const float* x      = (const float*)d_in[0];
    const float* omega  = (const float*)d_in[1];
    const float* G      = (const float*)d_in[2];
    const float* phase  = (const float*)d_in[3];
    const float* l1_w   = (const float*)d_in[4];
    const float* l1_b   = (const float*)d_in[5];
    const float* mu_w   = (const float*)d_in[6];
    const float* mu_b   = (const float*)d_in[7];
    const float* sg_w   = (const float*)d_in[8];
    const float* sg_b   = (const float*)d_in[9];
    const float* alnqg  = (const float*)d_in[10];
    const float* alnqb  = (const float*)d_in[11];
    const float* alnfg  = (const float*)d_in[12];
    const float* alnfb  = (const float*)d_in[13];
    const float* a_w1   = (const float*)d_in[14];
    const float* a_b1   = (const float*)d_in[15];
    const float* a_w2   = (const float*)d_in[16];
    const float* a_b2   = (const float*)d_in[17];
    const float* mln_g  = (const float*)d_in[18];
    const float* mln_b  = (const float*)d_in[19];
    const float* m_w1   = (const float*)d_in[20];
    const float* m_b1   = (const float*)d_in[21];
    const float* m_w2   = (const float*)d_in[22];
    const float* m_b2   = (const float*)d_in[23];
    const float* ro_w   = (const float*)d_in[24];
    const float* ro_b   = (const float*)d_in[25];
    float* out = (float*)d_out;

    __nv_bfloat16* wh; __nv_bfloat16* wl;
    float* Q;
    __nv_bfloat16* hh; __nv_bfloat16* hl;
    __nv_bfloat16* th; __nv_bfloat16* tl;
    {
        void* p;
        cudaGetSymbolAddress(&p, g_wh); wh = (__nv_bfloat16*)p;
        cudaGetSymbolAddress(&p, g_wl); wl = (__nv_bfloat16*)p;
        cudaGetSymbolAddress(&p, g_Q);  Q  = (float*)p;
        cudaGetSymbolAddress(&p, g_hh); hh = (__nv_bfloat16*)p;
        cudaGetSymbolAddress(&p, g_hl); hl = (__nv_bfloat16*)p;
        cudaGetSymbolAddress(&p, g_th); th = (__nv_bfloat16*)p;
        cudaGetSymbolAddress(&p, g_tl); tl = (__nv_bfloat16*)p;
    }

    cudaFuncSetAttribute(gemm_musig,
                         cudaFuncAttributeMaxDynamicSharedMemorySize, SMEM_BYTES);
    cudaFuncSetAttribute(gemm_ffn1<TDIM, FDIM>,
                         cudaFuncAttributeMaxDynamicSharedMemorySize, SMEM_BYTES);
    cudaFuncSetAttribute(gemm_ffn2<FDIM, TDIM>,
                         cudaFuncAttributeMaxDynamicSharedMemorySize, SMEM_BYTES);

    const int ew_blocks = (BATCH * TDIM) / 256;   // 16384
    const dim3 g_ms(1024 / 128, BATCH / 128);     // (8, 64)
    const dim3 g_f1(FDIM / 128, BATCH / 128);     // (16, 64)
    const dim3 g_f2(TDIM / 128, BATCH / 128);     // (4, 64)

    wsplit_all<<<WTOTAL / 256, 256>>>(mu_w, sg_w, a_w1, a_w2, m_w1, m_w2);
    prep_kernel<<<ew_blocks, 256>>>(x, omega, phase, l1_w, l1_b);

    for (int i = 0; i < NATTN; i++) {
        const size_t wms = (size_t)i * 1024 * 512;
        const size_t wft = (size_t)i * FDIM * TDIM;
        ln_kernel<<<BATCH / 8, 256>>>(Q, alnqg + i * TDIM, alnqb + i * TDIM);
        gemm_musig<<<g_ms, NTHREADS, SMEM_BYTES>>>(
            hh, hl, wh + MS_OFF + wms, wl + MS_OFF + wms,
            mu_b + i * TDIM, sg_b + i * TDIM, G, Q);
        ln_kernel<<<BATCH / 8, 256>>>(Q, alnfg + i * TDIM, alnfb + i * TDIM);
        gemm_ffn1<TDIM, FDIM><<<g_f1, NTHREADS, SMEM_BYTES>>>(
            hh, hl, wh + AW1_OFF + wft, wl + AW1_OFF + wft,
            a_b1 + i * FDIM, th, tl);
        gemm_ffn2<FDIM, TDIM><<<g_f2, NTHREADS, SMEM_BYTES>>>(
            th, tl, wh + AW2_OFF + wft, wl + AW2_OFF + wft,
            a_b2 + i * TDIM, Q);
    }
    for (int i = 0; i < NMLP; i++) {
        const size_t wft = (size_t)i * FDIM * TDIM;
        ln_kernel<<<BATCH / 8, 256>>>(Q, mln_g + i * TDIM, mln_b + i * TDIM);
        gemm_ffn1<TDIM, FDIM><<<g_f1, NTHREADS, SMEM_BYTES>>>(
            hh, hl, wh + MW1_OFF + wft, wl + MW1_OFF + wft,
            m_b1 + i * FDIM, th, tl);
        gemm_ffn2<FDIM, TDIM><<<g_f2, NTHREADS, SMEM_BYTES>>>(
            th, tl, wh + MW2_OFF + wft, wl + MW2_OFF + wft,
            m_b2 + i * TDIM, Q);
    }
    final_kernel<<<BATCH / 8, 256>>>(ro_w, ro_b, out);
}